// round 5
// baseline (speedup 1.0000x reference)
#include <cuda_runtime.h>
#include <cuda_bf16.h>
#include <math_constants.h>
#include <mma.h>
#include <cstdint>

using namespace nvcuda;

#define BB   8
#define CIN  512
#define NN   4096
#define DDIM 256
#define KKE  2048

// ---- scratch (device globals; no allocation allowed) ----
__device__ float g_ze[BB * DDIM * NN];                 // (B, D, N) conv output
__device__ float g_esq[KKE];                           // ||e_k||^2
__device__ int   g_minidx[BB * NN];                    // argmin indices
__device__ float g_zsum[KKE * DDIM];                   // segment sums
__device__ float g_nsum[KKE];                          // segment counts
__device__ __nv_bfloat16 g_embb[3u * KKE * DDIM];      // emb 3-way bf16 split [plane][k][d]
__device__ __nv_bfloat16 g_zeb[3u * BB * NN * DDIM];   // ze split+transposed [plane][b][n][d]

// ============================================================
// e_sq: one warp per codebook row
// ============================================================
__global__ void esq_kernel(const float* __restrict__ emb) {
    int warp = (blockIdx.x * blockDim.x + threadIdx.x) >> 5;
    int lane = threadIdx.x & 31;
    if (warp >= KKE) return;
    const float* row = emb + (size_t)warp * DDIM;
    float s = 0.f;
#pragma unroll
    for (int i = lane; i < DDIM; i += 32) { float v = row[i]; s += v * v; }
#pragma unroll
    for (int off = 16; off; off >>= 1) s += __shfl_down_sync(0xffffffffu, s, off);
    if (lane == 0) g_esq[warp] = s;
}

// ============================================================
// GEMM1: ze[b,d,n] = sum_c W[d,c] * z[b,c,n]   (R3 version)
// ============================================================
__global__ void __launch_bounds__(256, 2) gemm1_kernel(
    const float* __restrict__ z, const float* __restrict__ W)
{
    __shared__ float Ws[16][68];
    __shared__ float Zs[16][128];

    const int n0 = blockIdx.x * 128;
    const int d0 = blockIdx.y * 64;
    const int b  = blockIdx.z;
    const int tid = threadIdx.x;
    const int tk = tid >> 4;
    const int tn = tid & 15;

    float acc[4][8];
#pragma unroll
    for (int i = 0; i < 4; i++)
#pragma unroll
        for (int j = 0; j < 8; j++) acc[i][j] = 0.f;

    for (int c0 = 0; c0 < CIN; c0 += 16) {
#pragma unroll
        for (int i = 0; i < 4; i++) {
            int lin = tid + 256 * i;
            int dl = lin >> 4, cc = lin & 15;
            Ws[cc][dl] = W[(size_t)(d0 + dl) * CIN + c0 + cc];
        }
#pragma unroll
        for (int i = 0; i < 8; i++) {
            int lin = tid + 256 * i;
            int cc = lin >> 7, nl = lin & 127;
            Zs[cc][nl] = z[((size_t)b * CIN + c0 + cc) * NN + n0 + nl];
        }
        __syncthreads();
#pragma unroll
        for (int cc = 0; cc < 16; cc++) {
            float4 av = *(const float4*)&Ws[cc][tk * 4];
            float4 b0 = *(const float4*)&Zs[cc][tn * 8];
            float4 b1 = *(const float4*)&Zs[cc][tn * 8 + 4];
            float a[4] = {av.x, av.y, av.z, av.w};
            float bv[8] = {b0.x, b0.y, b0.z, b0.w, b1.x, b1.y, b1.z, b1.w};
#pragma unroll
            for (int i = 0; i < 4; i++)
#pragma unroll
                for (int j = 0; j < 8; j++) acc[i][j] += a[i] * bv[j];
        }
        __syncthreads();
    }
#pragma unroll
    for (int i = 0; i < 4; i++) {
        int d = d0 + tk * 4 + i;
        float* dst = &g_ze[((size_t)b * DDIM + d) * NN + n0 + tn * 8];
        *(float4*)dst       = make_float4(acc[i][0], acc[i][1], acc[i][2], acc[i][3]);
        *(float4*)(dst + 4) = make_float4(acc[i][4], acc[i][5], acc[i][6], acc[i][7]);
    }
}

// ============================================================
// 3-way exact bf16 split helpers
// ============================================================
__device__ __forceinline__ void split3(float x, __nv_bfloat16& h, __nv_bfloat16& m, __nv_bfloat16& l) {
    h = __float2bfloat16(x);
    float r1 = x - __bfloat162float(h);
    m = __float2bfloat16(r1);
    float r2 = r1 - __bfloat162float(m);
    l = __float2bfloat16(r2);
}

__global__ void split_emb_kernel(const float* __restrict__ emb) {
    int i = blockIdx.x * blockDim.x + threadIdx.x;
    if (i >= KKE * DDIM) return;
    __nv_bfloat16 h, m, l;
    split3(emb[i], h, m, l);
    g_embb[i] = h;
    g_embb[(size_t)KKE * DDIM + i] = m;
    g_embb[2u * KKE * DDIM + i] = l;
}

// transpose + split ze: g_ze (b,d,n) -> g_zeb [plane][b][n][d]
__global__ void split_ze_kernel() {
    __shared__ float tile[64][65];
    const int n0 = blockIdx.x * 64;
    const int d0 = blockIdx.y * 64;
    const int b  = blockIdx.z;
    const int tid = threadIdx.x;
    const size_t ZP = (size_t)BB * NN * DDIM;
#pragma unroll
    for (int i = 0; i < 16; i++) {
        int idx = tid + 256 * i;
        int r = idx >> 6, cc = idx & 63;
        tile[r][cc] = g_ze[((size_t)b * DDIM + d0 + r) * NN + n0 + cc];
    }
    __syncthreads();
#pragma unroll
    for (int i = 0; i < 16; i++) {
        int idx = tid + 256 * i;
        int nr = idx >> 6, dc = idx & 63;
        float x = tile[dc][nr];
        __nv_bfloat16 h, m, l;
        split3(x, h, m, l);
        size_t base = ((size_t)b * NN + n0 + nr) * DDIM + d0 + dc;
        g_zeb[base] = h;
        g_zeb[ZP + base] = m;
        g_zeb[2 * ZP + base] = l;
    }
}

// ============================================================
// wmma argmin kernel (bf16 HMMA, 6-term exact split)
//   cross[k,n] = sum_d e[k,d]*ze[b,d,n]
//   score = e_sq[k] - 2*cross ; argmin over k per column
// CTA: 64 n-cols x batch b. ze planes resident in smem; codes
// streamed in 64-k tiles. 8 warps = 2(k) x 4(n); warp tile 32k x 16n.
// ============================================================
#define ALD 264                       // padded leading dim (bf16 elems)
#define A_BYTES (3 * 64 * ALD * 2)    // 101376
#define OFF_B   A_BYTES
#define OFF_S   (2 * A_BYTES)         // 202752
#define SLD     72
#define S_BYTES (64 * SLD * 4)        // 18432
#define OFF_ESQ (OFF_S + S_BYTES)     // 221184
#define OFF_MIN (OFF_ESQ + 256)       // 221440
#define SMEM_TOTAL_ARG (OFF_MIN + 512) // 221952

__global__ void __launch_bounds__(256, 1) argmin_wmma_kernel()
{
    extern __shared__ char smem[];
    __nv_bfloat16* As = (__nv_bfloat16*)smem;                // [3][64][ALD]
    __nv_bfloat16* Bs = (__nv_bfloat16*)(smem + OFF_B);      // [3][64][ALD]
    float* S          = (float*)(smem + OFF_S);              // [64][SLD]
    float* esq_s      = (float*)(smem + OFF_ESQ);            // [64]
    unsigned long long* colmin = (unsigned long long*)(smem + OFF_MIN); // [64]

    const int tid = threadIdx.x;
    const int wid = tid >> 5;
    const int n0 = blockIdx.x * 64;
    const int b  = blockIdx.y;
    const int wk = wid >> 2;       // 0..1
    const int wn = wid & 3;        // 0..3

    if (tid < 64) colmin[tid] = 0xFFFFFFFFFFFFFFFFull;

    // ---- load resident ze planes: [p][n][d] rows of 256, pad to ALD ----
    {
        // 3*64 rows x 32 uint4 per row = 6144 vec loads
#pragma unroll
        for (int q = 0; q < 24; q++) {
            int i = tid + 256 * q;
            int row = i >> 5;            // p*64 + n  (0..191)
            int dv = i & 31;
            int p = row >> 6, nl = row & 63;
            const uint4 v = *(const uint4*)&g_zeb[(((size_t)p * BB + b) * NN + n0 + nl) * DDIM + dv * 8];
            *(uint4*)&Bs[(size_t)row * ALD + dv * 8] = v;
        }
    }
    __syncthreads();

    const int PA[6] = {0, 0, 1, 1, 0, 2};
    const int PB[6] = {0, 1, 0, 1, 2, 0};

    for (int k0 = 0; k0 < KKE; k0 += 64) {
        // ---- load A planes for this k-tile ----
#pragma unroll
        for (int q = 0; q < 24; q++) {
            int i = tid + 256 * q;
            int row = i >> 5;            // p*64 + k
            int dv = i & 31;
            int p = row >> 6, kl = row & 63;
            const uint4 v = *(const uint4*)&g_embb[((size_t)p * KKE + k0 + kl) * DDIM + dv * 8];
            *(uint4*)&As[(size_t)row * ALD + dv * 8] = v;
        }
        if (tid < 64) esq_s[tid] = g_esq[k0 + tid];
        __syncthreads();

        // ---- MMA: 6 plane pairs x 16 d-chunks ----
        wmma::fragment<wmma::accumulator, 16, 16, 16, float> acc0, acc1;
        wmma::fill_fragment(acc0, 0.0f);
        wmma::fill_fragment(acc1, 0.0f);
#pragma unroll
        for (int t = 0; t < 6; t++) {
            const __nv_bfloat16* Ab = As + (size_t)PA[t] * 64 * ALD;
            const __nv_bfloat16* Bb = Bs + (size_t)PB[t] * 64 * ALD;
#pragma unroll
            for (int dc = 0; dc < 16; dc++) {
                wmma::fragment<wmma::matrix_a, 16, 16, 16, __nv_bfloat16, wmma::row_major> a0, a1;
                wmma::fragment<wmma::matrix_b, 16, 16, 16, __nv_bfloat16, wmma::col_major> bfr;
                wmma::load_matrix_sync(bfr, Bb + (size_t)(wn * 16) * ALD + dc * 16, ALD);
                wmma::load_matrix_sync(a0, Ab + (size_t)(wk * 32) * ALD + dc * 16, ALD);
                wmma::load_matrix_sync(a1, Ab + (size_t)(wk * 32 + 16) * ALD + dc * 16, ALD);
                wmma::mma_sync(acc0, a0, bfr, acc0);
                wmma::mma_sync(acc1, a1, bfr, acc1);
            }
        }
        // ---- epilogue: scores -> smem, per-column packed min ----
        wmma::store_matrix_sync(&S[(size_t)(wk * 32) * SLD + wn * 16], acc0, SLD, wmma::mem_row_major);
        wmma::store_matrix_sync(&S[(size_t)(wk * 32 + 16) * SLD + wn * 16], acc1, SLD, wmma::mem_row_major);
        __syncthreads();
        {
            const int col = tid & 63;
            const int kq = tid >> 6;     // 0..3
            unsigned long long best = 0xFFFFFFFFFFFFFFFFull;
#pragma unroll
            for (int i = 0; i < 16; i++) {
                int kl = kq * 16 + i;
                float s = fmaf(-2.f, S[(size_t)kl * SLD + col], esq_s[kl]);
                uint32_t u = __float_as_uint(s);
                u = (u & 0x80000000u) ? ~u : (u | 0x80000000u);
                unsigned long long pk = ((unsigned long long)u << 32) | (unsigned)(k0 + kl);
                if (pk < best) best = pk;
            }
            atomicMin(&colmin[col], best);
        }
        __syncthreads();
    }
    if (tid < 64)
        g_minidx[(size_t)b * NN + n0 + tid] = (int)(colmin[tid] & 0xFFFFFFFFull);
}

// ============================================================
// zero scatter buffers
// ============================================================
__global__ void zero_kernel() {
    int total = KKE * DDIM + KKE;
    for (int i = blockIdx.x * blockDim.x + threadIdx.x; i < total;
         i += gridDim.x * blockDim.x) {
        if (i < KKE * DDIM) g_zsum[i] = 0.f;
        else g_nsum[i - KKE * DDIM] = 0.f;
    }
}

// ============================================================
// gather zq -> out, scatter-add ze into z_sum / n_sum
// ============================================================
__global__ void gs_kernel(const float* __restrict__ emb, float* __restrict__ out)
{
    const int b = blockIdx.y;
    const int n = blockIdx.x * 32 + threadIdx.x;
    const int ty = threadIdx.y;
    const int idx = g_minidx[(size_t)b * NN + n];
#pragma unroll 4
    for (int d = ty; d < DDIM; d += 8) {
        size_t zoff = ((size_t)b * DDIM + d) * NN + n;
        float zev = g_ze[zoff];
        out[zoff] = emb[(size_t)idx * DDIM + d];
        atomicAdd(&g_zsum[(size_t)idx * DDIM + d], zev);
    }
    if (ty == 0) atomicAdd(&g_nsum[idx], 1.0f);
}

// ============================================================
// EMA finalize -> tail of d_out
// ============================================================
__global__ void ema_kernel(const float* __restrict__ ema_numer,
                           const float* __restrict__ ema_denom,
                           float* __restrict__ out)
{
    const size_t OUT_OFF = (size_t)BB * DDIM * NN;
    int i = blockIdx.x * blockDim.x + threadIdx.x;
    if (i < KKE * DDIM)
        out[OUT_OFF + i] = 0.99f * ema_numer[i] + 0.01f * g_zsum[i];
    if (i < KKE)
        out[OUT_OFF + (size_t)KKE * DDIM + i] = 0.99f * ema_denom[i] + 0.01f * g_nsum[i];
}

// ============================================================
extern "C" void kernel_launch(void* const* d_in, const int* in_sizes, int n_in,
                              void* d_out, int out_size)
{
    const float* z         = (const float*)d_in[0];
    const float* W         = (const float*)d_in[1];
    const float* emb       = (const float*)d_in[2];
    const float* ema_numer = (const float*)d_in[3];
    const float* ema_denom = (const float*)d_in[4];
    float* out = (float*)d_out;
    (void)in_sizes; (void)n_in; (void)out_size;

    cudaFuncSetAttribute(argmin_wmma_kernel,
                         cudaFuncAttributeMaxDynamicSharedMemorySize, SMEM_TOTAL_ARG);

    // 1. codebook squared norms + bf16 split of emb
    esq_kernel<<<(KKE * 32 + 255) / 256, 256>>>(emb);
    split_emb_kernel<<<(KKE * DDIM + 255) / 256, 256>>>(emb);

    // 2. ze = W * z  (1x1 conv)
    {
        dim3 grid(NN / 128, DDIM / 64, BB);
        gemm1_kernel<<<grid, 256>>>(z, W);
    }

    // 3. split + transpose ze
    {
        dim3 grid(NN / 64, DDIM / 64, BB);
        split_ze_kernel<<<grid, 256>>>();
    }

    // 4. tensor-core (wmma bf16) distance GEMM + argmin
    {
        dim3 grid(NN / 64, BB);
        argmin_wmma_kernel<<<grid, 256, SMEM_TOTAL_ARG>>>();
    }

    // 5. zero scatter buffers
    zero_kernel<<<512, 256>>>();

    // 6. gather zq + scatter EMA statistics
    {
        dim3 grid(NN / 32, BB);
        dim3 blk(32, 8);
        gs_kernel<<<grid, blk>>>(emb, out);
    }

    // 7. EMA blend
    ema_kernel<<<(KKE * DDIM + 255) / 256, 256>>>(ema_numer, ema_denom, out);
}

// round 6
// speedup vs baseline: 1.2261x; 1.2261x over previous
#include <cuda_runtime.h>
#include <cuda_bf16.h>
#include <math_constants.h>
#include <cstdint>

#define BB   8
#define CIN  512
#define NN   4096
#define DDIM 256
#define KKE  2048

// ---- scratch (device globals; no allocation allowed) ----
__device__ float g_ze[BB * DDIM * NN];                 // (B, D, N) conv output
__device__ float g_esq[KKE];                           // ||e_k||^2
__device__ int   g_minidx[BB * NN];                    // argmin indices
__device__ float g_zsum[KKE * DDIM];                   // segment sums
__device__ float g_nsum[KKE];                          // segment counts
__device__ __nv_bfloat16 g_embb[3u * KKE * DDIM];      // emb 3-way bf16 split [plane][k][d]
__device__ __nv_bfloat16 g_zeb[3u * BB * NN * DDIM];   // ze split+transposed [plane][b][n][d]

__device__ __forceinline__ uint32_t smem_u32(const void* p) {
    uint32_t a;
    asm("{ .reg .u64 t; cvta.to.shared.u64 t, %1; cvt.u32.u64 %0, t; }" : "=r"(a) : "l"(p));
    return a;
}
__device__ __forceinline__ void ldsm_x4(uint32_t& r0, uint32_t& r1, uint32_t& r2, uint32_t& r3,
                                        uint32_t addr) {
    asm volatile("ldmatrix.sync.aligned.m8n8.x4.shared.b16 {%0,%1,%2,%3}, [%4];"
                 : "=r"(r0), "=r"(r1), "=r"(r2), "=r"(r3) : "r"(addr));
}
__device__ __forceinline__ void mma16816(float* c, const uint32_t* a, const uint32_t* b) {
    asm volatile("mma.sync.aligned.m16n8k16.row.col.f32.bf16.bf16.f32 "
                 "{%0,%1,%2,%3}, {%4,%5,%6,%7}, {%8,%9}, {%0,%1,%2,%3};"
                 : "+f"(c[0]), "+f"(c[1]), "+f"(c[2]), "+f"(c[3])
                 : "r"(a[0]), "r"(a[1]), "r"(a[2]), "r"(a[3]), "r"(b[0]), "r"(b[1]));
}

// ============================================================
// e_sq: one warp per codebook row
// ============================================================
__global__ void esq_kernel(const float* __restrict__ emb) {
    int warp = (blockIdx.x * blockDim.x + threadIdx.x) >> 5;
    int lane = threadIdx.x & 31;
    if (warp >= KKE) return;
    const float* row = emb + (size_t)warp * DDIM;
    float s = 0.f;
#pragma unroll
    for (int i = lane; i < DDIM; i += 32) { float v = row[i]; s += v * v; }
#pragma unroll
    for (int off = 16; off; off >>= 1) s += __shfl_down_sync(0xffffffffu, s, off);
    if (lane == 0) g_esq[warp] = s;
}

// ============================================================
// GEMM1: ze[b,d,n] = sum_c W[d,c] * z[b,c,n]   (R3 version)
// ============================================================
__global__ void __launch_bounds__(256, 2) gemm1_kernel(
    const float* __restrict__ z, const float* __restrict__ W)
{
    __shared__ float Ws[16][68];
    __shared__ float Zs[16][128];

    const int n0 = blockIdx.x * 128;
    const int d0 = blockIdx.y * 64;
    const int b  = blockIdx.z;
    const int tid = threadIdx.x;
    const int tk = tid >> 4;
    const int tn = tid & 15;

    float acc[4][8];
#pragma unroll
    for (int i = 0; i < 4; i++)
#pragma unroll
        for (int j = 0; j < 8; j++) acc[i][j] = 0.f;

    for (int c0 = 0; c0 < CIN; c0 += 16) {
#pragma unroll
        for (int i = 0; i < 4; i++) {
            int lin = tid + 256 * i;
            int dl = lin >> 4, cc = lin & 15;
            Ws[cc][dl] = W[(size_t)(d0 + dl) * CIN + c0 + cc];
        }
#pragma unroll
        for (int i = 0; i < 8; i++) {
            int lin = tid + 256 * i;
            int cc = lin >> 7, nl = lin & 127;
            Zs[cc][nl] = z[((size_t)b * CIN + c0 + cc) * NN + n0 + nl];
        }
        __syncthreads();
#pragma unroll
        for (int cc = 0; cc < 16; cc++) {
            float4 av = *(const float4*)&Ws[cc][tk * 4];
            float4 b0 = *(const float4*)&Zs[cc][tn * 8];
            float4 b1 = *(const float4*)&Zs[cc][tn * 8 + 4];
            float a[4] = {av.x, av.y, av.z, av.w};
            float bv[8] = {b0.x, b0.y, b0.z, b0.w, b1.x, b1.y, b1.z, b1.w};
#pragma unroll
            for (int i = 0; i < 4; i++)
#pragma unroll
                for (int j = 0; j < 8; j++) acc[i][j] += a[i] * bv[j];
        }
        __syncthreads();
    }
#pragma unroll
    for (int i = 0; i < 4; i++) {
        int d = d0 + tk * 4 + i;
        float* dst = &g_ze[((size_t)b * DDIM + d) * NN + n0 + tn * 8];
        *(float4*)dst       = make_float4(acc[i][0], acc[i][1], acc[i][2], acc[i][3]);
        *(float4*)(dst + 4) = make_float4(acc[i][4], acc[i][5], acc[i][6], acc[i][7]);
    }
}

// ============================================================
// 3-way exact bf16 split helpers
// ============================================================
__device__ __forceinline__ void split3(float x, __nv_bfloat16& h, __nv_bfloat16& m, __nv_bfloat16& l) {
    h = __float2bfloat16(x);
    float r1 = x - __bfloat162float(h);
    m = __float2bfloat16(r1);
    float r2 = r1 - __bfloat162float(m);
    l = __float2bfloat16(r2);
}

__global__ void split_emb_kernel(const float* __restrict__ emb) {
    int i = blockIdx.x * blockDim.x + threadIdx.x;
    if (i >= KKE * DDIM) return;
    __nv_bfloat16 h, m, l;
    split3(emb[i], h, m, l);
    g_embb[i] = h;
    g_embb[(size_t)KKE * DDIM + i] = m;
    g_embb[2u * KKE * DDIM + i] = l;
}

// transpose + split ze: g_ze (b,d,n) -> g_zeb [plane][b][n][d]
__global__ void split_ze_kernel() {
    __shared__ float tile[64][65];
    const int n0 = blockIdx.x * 64;
    const int d0 = blockIdx.y * 64;
    const int b  = blockIdx.z;
    const int tid = threadIdx.x;
    const size_t ZP = (size_t)BB * NN * DDIM;
#pragma unroll
    for (int i = 0; i < 16; i++) {
        int idx = tid + 256 * i;
        int r = idx >> 6, cc = idx & 63;
        tile[r][cc] = g_ze[((size_t)b * DDIM + d0 + r) * NN + n0 + cc];
    }
    __syncthreads();
#pragma unroll
    for (int i = 0; i < 16; i++) {
        int idx = tid + 256 * i;
        int nr = idx >> 6, dc = idx & 63;
        float x = tile[dc][nr];
        __nv_bfloat16 h, m, l;
        split3(x, h, m, l);
        size_t base = ((size_t)b * NN + n0 + nr) * DDIM + d0 + dc;
        g_zeb[base] = h;
        g_zeb[ZP + base] = m;
        g_zeb[2 * ZP + base] = l;
    }
}

// ============================================================
// mma.sync argmin kernel (bf16 HMMA, 6-term exact split,
// register-resident per-column argmin).
// CTA: 64 codes (streamed) x 64 n-cols (resident, full d=256).
// 4 warps = 2(M) x 2(N); warp tile M32 x N32; 8 fp32 mma accs.
// smem: A planes 3x64x256 bf16 (swizzled) | B same | colmin[64] u64.
// ============================================================
#define PLANE_BYTES 32768               // 64 rows * 512 B
#define AB_BYTES    (3 * PLANE_BYTES)   // 98304
#define OFF_COLMIN  (2 * AB_BYTES)      // 196608
#define SMEM_ARG    (OFF_COLMIN + 64 * 8)

__global__ void __launch_bounds__(128, 1) argmin_mma_kernel()
{
    extern __shared__ char smem[];
    char* As = smem;                 // [p][row(k)][swizzled d]
    char* Bs = smem + AB_BYTES;      // [p][row(n)][swizzled d]
    unsigned long long* colmin = (unsigned long long*)(smem + OFF_COLMIN);

    const int tid = threadIdx.x;
    const int wid = tid >> 5;
    const int L   = tid & 31;
    const int n0  = blockIdx.x * 64;
    const int b   = blockIdx.y;
    const int wM  = wid >> 1;        // 0..1
    const int wN  = wid & 1;         // 0..1

    const uint32_t As_u = smem_u32(As);
    const uint32_t Bs_u = smem_u32(Bs);

    if (tid < 64) colmin[tid] = 0xFFFFFFFFFFFFFFFFull;

    // ---- load resident B planes (swizzled) ----
#pragma unroll 8
    for (int q = 0; q < 48; q++) {
        int i = tid + 128 * q;               // 0..6143
        int p = i >> 11;
        int rem = i & 2047;
        int r = rem >> 5, c16 = rem & 31;
        uint4 v = *(const uint4*)&g_zeb[(((size_t)p * BB + b) * NN + n0 + r) * DDIM + c16 * 8];
        *(uint4*)(Bs + p * PLANE_BYTES + r * 512 + ((c16 ^ (r & 7)) * 16)) = v;
    }

    // per-lane static LDSM address components
    const int rowA_l = L & 15;               // local k row within 16
    const int kxA    = L >> 4;               // 0/1 -> d half chunk
    const int rowB_l = (L & 7) | ((L & 16) >> 1);   // local n row within 16
    const int kxB    = (L >> 3) & 1;

    const int PA[6] = {0, 0, 1, 1, 0, 2};
    const int PB[6] = {0, 1, 0, 1, 2, 0};

    unsigned long long best[8];
#pragma unroll
    for (int j = 0; j < 8; j++) best[j] = 0xFFFFFFFFFFFFFFFFull;

    for (int kt = 0; kt < 32; kt++) {
        const int k0 = kt * 64;
        __syncthreads();   // B ready (first iter) / previous tile's LDSMs done
        // ---- load A planes for this k-tile (swizzled) ----
#pragma unroll 8
        for (int q = 0; q < 48; q++) {
            int i = tid + 128 * q;
            int p = i >> 11;
            int rem = i & 2047;
            int r = rem >> 5, c16 = rem & 31;
            uint4 v = *(const uint4*)&g_embb[((size_t)p * KKE + k0 + r) * DDIM + c16 * 8];
            *(uint4*)(As + p * PLANE_BYTES + r * 512 + ((c16 ^ (r & 7)) * 16)) = v;
        }
        __syncthreads();

        float acc[2][4][4];   // [mfrag][nfrag(8-wide)][reg]
#pragma unroll
        for (int m = 0; m < 2; m++)
#pragma unroll
            for (int j = 0; j < 4; j++)
#pragma unroll
                for (int r = 0; r < 4; r++) acc[m][j][r] = 0.f;

#pragma unroll 1
        for (int t = 0; t < 6; t++) {
            const uint32_t Abase = As_u + PA[t] * PLANE_BYTES;
            const uint32_t Bbase = Bs_u + PB[t] * PLANE_BYTES;
#pragma unroll
            for (int dc = 0; dc < 16; dc++) {
                uint32_t a[2][4], bfr[2][4];
                {
                    int rA0 = wM * 32 + rowA_l;
                    int c16 = dc * 2 + kxA;
                    ldsm_x4(a[0][0], a[0][1], a[0][2], a[0][3],
                            Abase + rA0 * 512 + ((c16 ^ (rA0 & 7)) * 16));
                    int rA1 = rA0 + 16;
                    ldsm_x4(a[1][0], a[1][1], a[1][2], a[1][3],
                            Abase + rA1 * 512 + ((c16 ^ (rA1 & 7)) * 16));
                    int rB0 = wN * 32 + rowB_l;
                    int cB  = dc * 2 + kxB;
                    ldsm_x4(bfr[0][0], bfr[0][1], bfr[0][2], bfr[0][3],
                            Bbase + rB0 * 512 + ((cB ^ (rB0 & 7)) * 16));
                    int rB1 = rB0 + 16;
                    ldsm_x4(bfr[1][0], bfr[1][1], bfr[1][2], bfr[1][3],
                            Bbase + rB1 * 512 + ((cB ^ (rB1 & 7)) * 16));
                }
#pragma unroll
                for (int m = 0; m < 2; m++) {
                    mma16816(acc[m][0], a[m], &bfr[0][0]);
                    mma16816(acc[m][1], a[m], &bfr[0][2]);
                    mma16816(acc[m][2], a[m], &bfr[1][0]);
                    mma16816(acc[m][3], a[m], &bfr[1][2]);
                }
            }
        }
        // ---- register epilogue: scores + running per-column min ----
#pragma unroll
        for (int m = 0; m < 2; m++) {
            const int kg0 = k0 + wM * 32 + m * 16 + (L >> 2);
            const int kg1 = kg0 + 8;
            const float e0 = __ldg(&g_esq[kg0]);
            const float e1 = __ldg(&g_esq[kg1]);
#pragma unroll
            for (int j = 0; j < 4; j++) {
                float s0 = fmaf(-2.f, acc[m][j][0], e0);
                float s1 = fmaf(-2.f, acc[m][j][1], e0);
                float s2 = fmaf(-2.f, acc[m][j][2], e1);
                float s3 = fmaf(-2.f, acc[m][j][3], e1);
                uint32_t u0 = __float_as_uint(s0); u0 = (u0 & 0x80000000u) ? ~u0 : (u0 | 0x80000000u);
                uint32_t u1 = __float_as_uint(s1); u1 = (u1 & 0x80000000u) ? ~u1 : (u1 | 0x80000000u);
                uint32_t u2 = __float_as_uint(s2); u2 = (u2 & 0x80000000u) ? ~u2 : (u2 | 0x80000000u);
                uint32_t u3 = __float_as_uint(s3); u3 = (u3 & 0x80000000u) ? ~u3 : (u3 | 0x80000000u);
                unsigned long long p0 = ((unsigned long long)u0 << 32) | (unsigned)kg0;
                unsigned long long p1 = ((unsigned long long)u1 << 32) | (unsigned)kg0;
                unsigned long long p2 = ((unsigned long long)u2 << 32) | (unsigned)kg1;
                unsigned long long p3 = ((unsigned long long)u3 << 32) | (unsigned)kg1;
                if (p0 < best[2 * j])     best[2 * j]     = p0;
                if (p2 < best[2 * j])     best[2 * j]     = p2;
                if (p1 < best[2 * j + 1]) best[2 * j + 1] = p1;
                if (p3 < best[2 * j + 1]) best[2 * j + 1] = p3;
            }
        }
    }
    // ---- final reduction: lanes sharing a column (same L%4) ----
#pragma unroll
    for (int j = 0; j < 8; j++) {
#pragma unroll
        for (int off = 4; off <= 16; off <<= 1) {
            unsigned long long o = __shfl_xor_sync(0xffffffffu, best[j], off);
            if (o < best[j]) best[j] = o;
        }
    }
    if (L < 4) {
#pragma unroll
        for (int j = 0; j < 8; j++) {
            int col = wN * 32 + (j >> 1) * 8 + 2 * L + (j & 1);
            atomicMin(&colmin[col], best[j]);
        }
    }
    __syncthreads();
    if (tid < 64)
        g_minidx[(size_t)b * NN + n0 + tid] = (int)(colmin[tid] & 0xFFFFFFFFull);
}

// ============================================================
// zero scatter buffers
// ============================================================
__global__ void zero_kernel() {
    int total = KKE * DDIM + KKE;
    for (int i = blockIdx.x * blockDim.x + threadIdx.x; i < total;
         i += gridDim.x * blockDim.x) {
        if (i < KKE * DDIM) g_zsum[i] = 0.f;
        else g_nsum[i - KKE * DDIM] = 0.f;
    }
}

// ============================================================
// gather zq -> out, scatter-add ze into z_sum / n_sum
// ============================================================
__global__ void gs_kernel(const float* __restrict__ emb, float* __restrict__ out)
{
    const int b = blockIdx.y;
    const int n = blockIdx.x * 32 + threadIdx.x;
    const int ty = threadIdx.y;
    const int idx = g_minidx[(size_t)b * NN + n];
#pragma unroll 4
    for (int d = ty; d < DDIM; d += 8) {
        size_t zoff = ((size_t)b * DDIM + d) * NN + n;
        float zev = g_ze[zoff];
        out[zoff] = emb[(size_t)idx * DDIM + d];
        atomicAdd(&g_zsum[(size_t)idx * DDIM + d], zev);
    }
    if (ty == 0) atomicAdd(&g_nsum[idx], 1.0f);
}

// ============================================================
// EMA finalize -> tail of d_out
// ============================================================
__global__ void ema_kernel(const float* __restrict__ ema_numer,
                           const float* __restrict__ ema_denom,
                           float* __restrict__ out)
{
    const size_t OUT_OFF = (size_t)BB * DDIM * NN;
    int i = blockIdx.x * blockDim.x + threadIdx.x;
    if (i < KKE * DDIM)
        out[OUT_OFF + i] = 0.99f * ema_numer[i] + 0.01f * g_zsum[i];
    if (i < KKE)
        out[OUT_OFF + (size_t)KKE * DDIM + i] = 0.99f * ema_denom[i] + 0.01f * g_nsum[i];
}

// ============================================================
extern "C" void kernel_launch(void* const* d_in, const int* in_sizes, int n_in,
                              void* d_out, int out_size)
{
    const float* z         = (const float*)d_in[0];
    const float* W         = (const float*)d_in[1];
    const float* emb       = (const float*)d_in[2];
    const float* ema_numer = (const float*)d_in[3];
    const float* ema_denom = (const float*)d_in[4];
    float* out = (float*)d_out;
    (void)in_sizes; (void)n_in; (void)out_size;

    cudaFuncSetAttribute(argmin_mma_kernel,
                         cudaFuncAttributeMaxDynamicSharedMemorySize, SMEM_ARG);

    // 1. codebook squared norms + bf16 split of emb
    esq_kernel<<<(KKE * 32 + 255) / 256, 256>>>(emb);
    split_emb_kernel<<<(KKE * DDIM + 255) / 256, 256>>>(emb);

    // 2. ze = W * z  (1x1 conv)
    {
        dim3 grid(NN / 128, DDIM / 64, BB);
        gemm1_kernel<<<grid, 256>>>(z, W);
    }

    // 3. split + transpose ze
    {
        dim3 grid(NN / 64, DDIM / 64, BB);
        split_ze_kernel<<<grid, 256>>>();
    }

    // 4. tensor-core (mma.sync bf16) distance GEMM + argmin
    {
        dim3 grid(NN / 64, BB);
        argmin_mma_kernel<<<grid, 128, SMEM_ARG>>>();
    }

    // 5. zero scatter buffers
    zero_kernel<<<512, 256>>>();

    // 6. gather zq + scatter EMA statistics
    {
        dim3 grid(NN / 32, BB);
        dim3 blk(32, 8);
        gs_kernel<<<grid, blk>>>(emb, out);
    }

    // 7. EMA blend
    ema_kernel<<<(KKE * DDIM + 255) / 256, 256>>>(ema_numer, ema_denom, out);
}

// round 7
// speedup vs baseline: 1.3200x; 1.0766x over previous
#include <cuda_runtime.h>
#include <cuda_bf16.h>
#include <math_constants.h>
#include <cstdint>

#define BB   8
#define CIN  512
#define NN   4096
#define DDIM 256
#define KKE  2048

// ---- scratch (device globals; no allocation allowed) ----
__device__ float g_ze[BB * DDIM * NN];                 // (B, D, N) conv output
__device__ float g_esq[KKE];                           // ||e_k||^2
__device__ int   g_minidx[BB * NN];                    // argmin indices
__device__ float g_zsum[KKE * DDIM];                   // segment sums
__device__ float g_nsum[KKE];                          // segment counts
__device__ __nv_bfloat16 g_embb[3u * KKE * DDIM];      // emb 3-way bf16 split [plane][k][d]
__device__ __nv_bfloat16 g_zeb[3u * BB * NN * DDIM];   // ze split+transposed [plane][b][n][d]

__device__ __forceinline__ uint32_t smem_u32(const void* p) {
    uint32_t a;
    asm("{ .reg .u64 t; cvta.to.shared.u64 t, %1; cvt.u32.u64 %0, t; }" : "=r"(a) : "l"(p));
    return a;
}
__device__ __forceinline__ void ldsm_x4(uint32_t& r0, uint32_t& r1, uint32_t& r2, uint32_t& r3,
                                        uint32_t addr) {
    asm volatile("ldmatrix.sync.aligned.m8n8.x4.shared.b16 {%0,%1,%2,%3}, [%4];"
                 : "=r"(r0), "=r"(r1), "=r"(r2), "=r"(r3) : "r"(addr));
}
__device__ __forceinline__ void mma16816(float* c, const uint32_t* a, const uint32_t* b) {
    asm volatile("mma.sync.aligned.m16n8k16.row.col.f32.bf16.bf16.f32 "
                 "{%0,%1,%2,%3}, {%4,%5,%6,%7}, {%8,%9}, {%0,%1,%2,%3};"
                 : "+f"(c[0]), "+f"(c[1]), "+f"(c[2]), "+f"(c[3])
                 : "r"(a[0]), "r"(a[1]), "r"(a[2]), "r"(a[3]), "r"(b[0]), "r"(b[1]));
}

// ============================================================
// e_sq: one warp per codebook row
// ============================================================
__global__ void esq_kernel(const float* __restrict__ emb) {
    int warp = (blockIdx.x * blockDim.x + threadIdx.x) >> 5;
    int lane = threadIdx.x & 31;
    if (warp >= KKE) return;
    const float* row = emb + (size_t)warp * DDIM;
    float s = 0.f;
#pragma unroll
    for (int i = lane; i < DDIM; i += 32) { float v = row[i]; s += v * v; }
#pragma unroll
    for (int off = 16; off; off >>= 1) s += __shfl_down_sync(0xffffffffu, s, off);
    if (lane == 0) g_esq[warp] = s;
}

// ============================================================
// GEMM1: ze[b,d,n] = sum_c W[d,c] * z[b,c,n]   (R3 version)
// ============================================================
__global__ void __launch_bounds__(256, 2) gemm1_kernel(
    const float* __restrict__ z, const float* __restrict__ W)
{
    __shared__ float Ws[16][68];
    __shared__ float Zs[16][128];

    const int n0 = blockIdx.x * 128;
    const int d0 = blockIdx.y * 64;
    const int b  = blockIdx.z;
    const int tid = threadIdx.x;
    const int tk = tid >> 4;
    const int tn = tid & 15;

    float acc[4][8];
#pragma unroll
    for (int i = 0; i < 4; i++)
#pragma unroll
        for (int j = 0; j < 8; j++) acc[i][j] = 0.f;

    for (int c0 = 0; c0 < CIN; c0 += 16) {
#pragma unroll
        for (int i = 0; i < 4; i++) {
            int lin = tid + 256 * i;
            int dl = lin >> 4, cc = lin & 15;
            Ws[cc][dl] = W[(size_t)(d0 + dl) * CIN + c0 + cc];
        }
#pragma unroll
        for (int i = 0; i < 8; i++) {
            int lin = tid + 256 * i;
            int cc = lin >> 7, nl = lin & 127;
            Zs[cc][nl] = z[((size_t)b * CIN + c0 + cc) * NN + n0 + nl];
        }
        __syncthreads();
#pragma unroll
        for (int cc = 0; cc < 16; cc++) {
            float4 av = *(const float4*)&Ws[cc][tk * 4];
            float4 b0 = *(const float4*)&Zs[cc][tn * 8];
            float4 b1 = *(const float4*)&Zs[cc][tn * 8 + 4];
            float a[4] = {av.x, av.y, av.z, av.w};
            float bv[8] = {b0.x, b0.y, b0.z, b0.w, b1.x, b1.y, b1.z, b1.w};
#pragma unroll
            for (int i = 0; i < 4; i++)
#pragma unroll
                for (int j = 0; j < 8; j++) acc[i][j] += a[i] * bv[j];
        }
        __syncthreads();
    }
#pragma unroll
    for (int i = 0; i < 4; i++) {
        int d = d0 + tk * 4 + i;
        float* dst = &g_ze[((size_t)b * DDIM + d) * NN + n0 + tn * 8];
        *(float4*)dst       = make_float4(acc[i][0], acc[i][1], acc[i][2], acc[i][3]);
        *(float4*)(dst + 4) = make_float4(acc[i][4], acc[i][5], acc[i][6], acc[i][7]);
    }
}

// ============================================================
// 3-way exact bf16 split helpers
// ============================================================
__device__ __forceinline__ void split3(float x, __nv_bfloat16& h, __nv_bfloat16& m, __nv_bfloat16& l) {
    h = __float2bfloat16(x);
    float r1 = x - __bfloat162float(h);
    m = __float2bfloat16(r1);
    float r2 = r1 - __bfloat162float(m);
    l = __float2bfloat16(r2);
}

__global__ void split_emb_kernel(const float* __restrict__ emb) {
    int i = blockIdx.x * blockDim.x + threadIdx.x;
    if (i >= KKE * DDIM) return;
    __nv_bfloat16 h, m, l;
    split3(emb[i], h, m, l);
    g_embb[i] = h;
    g_embb[(size_t)KKE * DDIM + i] = m;
    g_embb[2u * KKE * DDIM + i] = l;
}

// transpose + split ze: g_ze (b,d,n) -> g_zeb [plane][b][n][d]
__global__ void split_ze_kernel() {
    __shared__ float tile[64][65];
    const int n0 = blockIdx.x * 64;
    const int d0 = blockIdx.y * 64;
    const int b  = blockIdx.z;
    const int tid = threadIdx.x;
    const size_t ZP = (size_t)BB * NN * DDIM;
#pragma unroll
    for (int i = 0; i < 16; i++) {
        int idx = tid + 256 * i;
        int r = idx >> 6, cc = idx & 63;
        tile[r][cc] = g_ze[((size_t)b * DDIM + d0 + r) * NN + n0 + cc];
    }
    __syncthreads();
#pragma unroll
    for (int i = 0; i < 16; i++) {
        int idx = tid + 256 * i;
        int nr = idx >> 6, dc = idx & 63;
        float x = tile[dc][nr];
        __nv_bfloat16 h, m, l;
        split3(x, h, m, l);
        size_t base = ((size_t)b * NN + n0 + nr) * DDIM + d0 + dc;
        g_zeb[base] = h;
        g_zeb[ZP + base] = m;
        g_zeb[2 * ZP + base] = l;
    }
}

// ============================================================
// mma.sync argmin kernel v3 (bf16 HMMA, 6-term exact split,
// register-resident per-column argmin, 8 warps / 2 per SMSP).
// CTA: k-tile 128 codes (streamed, d-chunked by 128) x 64 n-cols
// (resident, full d=256). 8 warps = 4(M) x 2(N); warp tile 32k x 32n.
// smem: A 3 planes x 128k x 256B (d-chunk) | B 3 planes x 64n x 512B.
// ============================================================
#define PLANE_B 32768                    // A: 128r*256B ; B: 64r*512B
#define A_BYTES (3 * PLANE_B)            // 98304
#define OFF_B   A_BYTES
#define OFF_COLMIN (2 * A_BYTES)         // 196608
#define SMEM_ARG   (OFF_COLMIN + 64 * 8) // 197120

__global__ void __launch_bounds__(256, 1) argmin_mma_kernel()
{
    extern __shared__ char smem[];
    char* As = smem;                 // [p][k_local(128)][swizzled 256B]
    char* Bs = smem + OFF_B;         // [p][n_local(64)][swizzled 512B]
    unsigned long long* colmin = (unsigned long long*)(smem + OFF_COLMIN);

    const int tid = threadIdx.x;
    const int wid = tid >> 5;
    const int L   = tid & 31;
    const int n0  = blockIdx.x * 64;
    const int b   = blockIdx.y;
    const int wM  = wid >> 1;        // 0..3
    const int wN  = wid & 1;         // 0..1

    const uint32_t As_u = smem_u32(As);
    const uint32_t Bs_u = smem_u32(Bs);

    if (tid < 64) colmin[tid] = 0xFFFFFFFFFFFFFFFFull;

    // ---- load resident B planes (full d, swizzled) ----
#pragma unroll 4
    for (int q = 0; q < 24; q++) {
        int i = tid + 256 * q;               // 0..6143
        int p = i >> 11;
        int rem = i & 2047;
        int r = rem >> 5, c16 = rem & 31;    // 64 rows x 32 granules
        uint4 v = *(const uint4*)&g_zeb[(((size_t)p * BB + b) * NN + n0 + r) * DDIM + c16 * 8];
        *(uint4*)(Bs + p * PLANE_B + r * 512 + ((c16 ^ (r & 7)) * 16)) = v;
    }

    // per-lane static LDSM address components (validated in R6)
    const int rowA_l = L & 15;               // local k row within 16
    const int kxA    = L >> 4;               // 0/1 -> k16 half granule
    const int rowB_l = (L & 7) | ((L & 16) >> 1);   // local n row within 16
    const int kxB    = (L >> 3) & 1;

    const int PA[6] = {0, 0, 1, 1, 0, 2};
    const int PB[6] = {0, 1, 0, 1, 2, 0};

    unsigned long long best[8];
#pragma unroll
    for (int j = 0; j < 8; j++) best[j] = 0xFFFFFFFFFFFFFFFFull;

    for (int kt = 0; kt < 16; kt++) {
        const int k0 = kt * 128;

        float acc[2][4][4];   // [mfrag][nfrag(8-wide)][reg]
#pragma unroll
        for (int m = 0; m < 2; m++)
#pragma unroll
            for (int j = 0; j < 4; j++)
#pragma unroll
                for (int r = 0; r < 4; r++) acc[m][j][r] = 0.f;

#pragma unroll 1
        for (int dch = 0; dch < 2; dch++) {
            __syncthreads();   // prior compute done / B ready on first pass
            // ---- load A d-chunk: 3 planes x 128 rows x 256B ----
#pragma unroll 4
            for (int q = 0; q < 24; q++) {
                int i = tid + 256 * q;           // 0..6143
                int p = i >> 11;
                int rem = i & 2047;
                int r = rem >> 4, g = rem & 15;  // 128 rows x 16 granules
                uint4 v = *(const uint4*)&g_embb[((size_t)p * KKE + k0 + r) * DDIM + dch * 128 + g * 8];
                *(uint4*)(As + p * PLANE_B + r * 256 + ((g ^ (r & 7)) * 16)) = v;
            }
            __syncthreads();

#pragma unroll 1
            for (int t = 0; t < 6; t++) {
                const uint32_t Abase = As_u + PA[t] * PLANE_B;
                const uint32_t Bbase = Bs_u + PB[t] * PLANE_B;
#pragma unroll
                for (int dc = 0; dc < 8; dc++) {
                    uint32_t a[2][4], bfr[2][4];
                    {
                        int rA0 = wM * 32 + rowA_l;
                        int gA  = dc * 2 + kxA;
                        ldsm_x4(a[0][0], a[0][1], a[0][2], a[0][3],
                                Abase + rA0 * 256 + ((gA ^ (rA0 & 7)) * 16));
                        int rA1 = rA0 + 16;
                        ldsm_x4(a[1][0], a[1][1], a[1][2], a[1][3],
                                Abase + rA1 * 256 + ((gA ^ (rA1 & 7)) * 16));
                        int rB0 = wN * 32 + rowB_l;
                        int gB  = dch * 16 + dc * 2 + kxB;
                        ldsm_x4(bfr[0][0], bfr[0][1], bfr[0][2], bfr[0][3],
                                Bbase + rB0 * 512 + ((gB ^ (rB0 & 7)) * 16));
                        int rB1 = rB0 + 16;
                        ldsm_x4(bfr[1][0], bfr[1][1], bfr[1][2], bfr[1][3],
                                Bbase + rB1 * 512 + ((gB ^ (rB1 & 7)) * 16));
                    }
#pragma unroll
                    for (int m = 0; m < 2; m++) {
                        mma16816(acc[m][0], a[m], &bfr[0][0]);
                        mma16816(acc[m][1], a[m], &bfr[0][2]);
                        mma16816(acc[m][2], a[m], &bfr[1][0]);
                        mma16816(acc[m][3], a[m], &bfr[1][2]);
                    }
                }
            }
        }
        // ---- register epilogue: scores + running per-column min ----
#pragma unroll
        for (int m = 0; m < 2; m++) {
            const int kg0 = k0 + wM * 32 + m * 16 + (L >> 2);
            const int kg1 = kg0 + 8;
            const float e0 = __ldg(&g_esq[kg0]);
            const float e1 = __ldg(&g_esq[kg1]);
#pragma unroll
            for (int j = 0; j < 4; j++) {
                float s0 = fmaf(-2.f, acc[m][j][0], e0);
                float s1 = fmaf(-2.f, acc[m][j][1], e0);
                float s2 = fmaf(-2.f, acc[m][j][2], e1);
                float s3 = fmaf(-2.f, acc[m][j][3], e1);
                uint32_t u0 = __float_as_uint(s0); u0 = (u0 & 0x80000000u) ? ~u0 : (u0 | 0x80000000u);
                uint32_t u1 = __float_as_uint(s1); u1 = (u1 & 0x80000000u) ? ~u1 : (u1 | 0x80000000u);
                uint32_t u2 = __float_as_uint(s2); u2 = (u2 & 0x80000000u) ? ~u2 : (u2 | 0x80000000u);
                uint32_t u3 = __float_as_uint(s3); u3 = (u3 & 0x80000000u) ? ~u3 : (u3 | 0x80000000u);
                unsigned long long p0 = ((unsigned long long)u0 << 32) | (unsigned)kg0;
                unsigned long long p1 = ((unsigned long long)u1 << 32) | (unsigned)kg0;
                unsigned long long p2 = ((unsigned long long)u2 << 32) | (unsigned)kg1;
                unsigned long long p3 = ((unsigned long long)u3 << 32) | (unsigned)kg1;
                if (p0 < best[2 * j])     best[2 * j]     = p0;
                if (p2 < best[2 * j])     best[2 * j]     = p2;
                if (p1 < best[2 * j + 1]) best[2 * j + 1] = p1;
                if (p3 < best[2 * j + 1]) best[2 * j + 1] = p3;
            }
        }
    }
    // ---- final reduction: lanes sharing a column (same L%4) ----
#pragma unroll
    for (int j = 0; j < 8; j++) {
#pragma unroll
        for (int off = 4; off <= 16; off <<= 1) {
            unsigned long long o = __shfl_xor_sync(0xffffffffu, best[j], off);
            if (o < best[j]) best[j] = o;
        }
    }
    if (L < 4) {
#pragma unroll
        for (int j = 0; j < 8; j++) {
            int col = wN * 32 + (j >> 1) * 8 + 2 * L + (j & 1);
            atomicMin(&colmin[col], best[j]);
        }
    }
    __syncthreads();
    if (tid < 64)
        g_minidx[(size_t)b * NN + n0 + tid] = (int)(colmin[tid] & 0xFFFFFFFFull);
}

// ============================================================
// zero scatter buffers
// ============================================================
__global__ void zero_kernel() {
    int total = KKE * DDIM + KKE;
    for (int i = blockIdx.x * blockDim.x + threadIdx.x; i < total;
         i += gridDim.x * blockDim.x) {
        if (i < KKE * DDIM) g_zsum[i] = 0.f;
        else g_nsum[i - KKE * DDIM] = 0.f;
    }
}

// ============================================================
// gather zq -> out, scatter-add ze into z_sum / n_sum
// ============================================================
__global__ void gs_kernel(const float* __restrict__ emb, float* __restrict__ out)
{
    const int b = blockIdx.y;
    const int n = blockIdx.x * 32 + threadIdx.x;
    const int ty = threadIdx.y;
    const int idx = g_minidx[(size_t)b * NN + n];
#pragma unroll 4
    for (int d = ty; d < DDIM; d += 8) {
        size_t zoff = ((size_t)b * DDIM + d) * NN + n;
        float zev = g_ze[zoff];
        out[zoff] = emb[(size_t)idx * DDIM + d];
        atomicAdd(&g_zsum[(size_t)idx * DDIM + d], zev);
    }
    if (ty == 0) atomicAdd(&g_nsum[idx], 1.0f);
}

// ============================================================
// EMA finalize -> tail of d_out
// ============================================================
__global__ void ema_kernel(const float* __restrict__ ema_numer,
                           const float* __restrict__ ema_denom,
                           float* __restrict__ out)
{
    const size_t OUT_OFF = (size_t)BB * DDIM * NN;
    int i = blockIdx.x * blockDim.x + threadIdx.x;
    if (i < KKE * DDIM)
        out[OUT_OFF + i] = 0.99f * ema_numer[i] + 0.01f * g_zsum[i];
    if (i < KKE)
        out[OUT_OFF + (size_t)KKE * DDIM + i] = 0.99f * ema_denom[i] + 0.01f * g_nsum[i];
}

// ============================================================
extern "C" void kernel_launch(void* const* d_in, const int* in_sizes, int n_in,
                              void* d_out, int out_size)
{
    const float* z         = (const float*)d_in[0];
    const float* W         = (const float*)d_in[1];
    const float* emb       = (const float*)d_in[2];
    const float* ema_numer = (const float*)d_in[3];
    const float* ema_denom = (const float*)d_in[4];
    float* out = (float*)d_out;
    (void)in_sizes; (void)n_in; (void)out_size;

    cudaFuncSetAttribute(argmin_mma_kernel,
                         cudaFuncAttributeMaxDynamicSharedMemorySize, SMEM_ARG);

    // 1. codebook squared norms + bf16 split of emb
    esq_kernel<<<(KKE * 32 + 255) / 256, 256>>>(emb);
    split_emb_kernel<<<(KKE * DDIM + 255) / 256, 256>>>(emb);

    // 2. ze = W * z  (1x1 conv)
    {
        dim3 grid(NN / 128, DDIM / 64, BB);
        gemm1_kernel<<<grid, 256>>>(z, W);
    }

    // 3. split + transpose ze
    {
        dim3 grid(NN / 64, DDIM / 64, BB);
        split_ze_kernel<<<grid, 256>>>();
    }

    // 4. tensor-core (mma.sync bf16) distance GEMM + argmin
    {
        dim3 grid(NN / 64, BB);
        argmin_mma_kernel<<<grid, 256, SMEM_ARG>>>();
    }

    // 5. zero scatter buffers
    zero_kernel<<<512, 256>>>();

    // 6. gather zq + scatter EMA statistics
    {
        dim3 grid(NN / 32, BB);
        dim3 blk(32, 8);
        gs_kernel<<<grid, blk>>>(emb, out);
    }

    // 7. EMA blend
    ema_kernel<<<(KKE * DDIM + 255) / 256, 256>>>(ema_numer, ema_denom, out);
}

// round 8
// speedup vs baseline: 1.6652x; 1.2614x over previous
#include <cuda_runtime.h>
#include <cuda_bf16.h>
#include <math_constants.h>
#include <cstdint>

#define BB   8
#define CIN  512
#define NN   4096
#define DDIM 256
#define KKE  2048
#define CAP  16
#define C0_BOUND 1.5e-4f

// ---- scratch (device globals; no allocation allowed) ----
__device__ float g_ze[BB * DDIM * NN];                 // (B, D, N) conv output
__device__ float g_zet[BB * NN * DDIM];                // ze fp32 transposed [b][n][d]
__device__ float g_esq[KKE];                           // ||e_k||^2
__device__ float g_enorm[KKE];                         // ||e_k||
__device__ float g_znorm[BB * NN];                     // ||ze_n||
__device__ int   g_minidx[BB * NN];                    // argmin indices
__device__ float g_zsum[KKE * DDIM];                   // segment sums
__device__ float g_nsum[KKE];                          // segment counts
__device__ __nv_bfloat16 g_embb[2u * KKE * DDIM];      // emb 2-plane bf16 split
__device__ __nv_bfloat16 g_zeb[2u * BB * NN * DDIM];   // ze 2-plane split+transposed
__device__ unsigned int g_cand[(size_t)BB * NN * CAP]; // candidate lists
__device__ unsigned int g_ccnt[BB * NN];               // candidate counts

__device__ __forceinline__ uint32_t smem_u32(const void* p) {
    uint32_t a;
    asm("{ .reg .u64 t; cvta.to.shared.u64 t, %1; cvt.u32.u64 %0, t; }" : "=r"(a) : "l"(p));
    return a;
}
__device__ __forceinline__ void ldsm_x4(uint32_t& r0, uint32_t& r1, uint32_t& r2, uint32_t& r3,
                                        uint32_t addr) {
    asm volatile("ldmatrix.sync.aligned.m8n8.x4.shared.b16 {%0,%1,%2,%3}, [%4];"
                 : "=r"(r0), "=r"(r1), "=r"(r2), "=r"(r3) : "r"(addr));
}
__device__ __forceinline__ void mma16816(float* c, const uint32_t* a, const uint32_t* b) {
    asm volatile("mma.sync.aligned.m16n8k16.row.col.f32.bf16.bf16.f32 "
                 "{%0,%1,%2,%3}, {%4,%5,%6,%7}, {%8,%9}, {%0,%1,%2,%3};"
                 : "+f"(c[0]), "+f"(c[1]), "+f"(c[2]), "+f"(c[3])
                 : "r"(a[0]), "r"(a[1]), "r"(a[2]), "r"(a[3]), "r"(b[0]), "r"(b[1]));
}
__device__ __forceinline__ uint32_t orderable(float s) {
    uint32_t u = __float_as_uint(s);
    return (u & 0x80000000u) ? ~u : (u | 0x80000000u);
}

// ============================================================
// e_sq + e_norm: one warp per codebook row
// ============================================================
__global__ void esq_kernel(const float* __restrict__ emb) {
    int warp = (blockIdx.x * blockDim.x + threadIdx.x) >> 5;
    int lane = threadIdx.x & 31;
    if (warp >= KKE) return;
    const float* row = emb + (size_t)warp * DDIM;
    float s = 0.f;
#pragma unroll
    for (int i = lane; i < DDIM; i += 32) { float v = row[i]; s += v * v; }
#pragma unroll
    for (int off = 16; off; off >>= 1) s += __shfl_down_sync(0xffffffffu, s, off);
    if (lane == 0) { g_esq[warp] = s; g_enorm[warp] = sqrtf(s); }
}

// ============================================================
// GEMM1: ze[b,d,n] = sum_c W[d,c] * z[b,c,n]   (R3 version)
// ============================================================
__global__ void __launch_bounds__(256, 2) gemm1_kernel(
    const float* __restrict__ z, const float* __restrict__ W)
{
    __shared__ float Ws[16][68];
    __shared__ float Zs[16][128];

    const int n0 = blockIdx.x * 128;
    const int d0 = blockIdx.y * 64;
    const int b  = blockIdx.z;
    const int tid = threadIdx.x;
    const int tk = tid >> 4;
    const int tn = tid & 15;

    float acc[4][8];
#pragma unroll
    for (int i = 0; i < 4; i++)
#pragma unroll
        for (int j = 0; j < 8; j++) acc[i][j] = 0.f;

    for (int c0 = 0; c0 < CIN; c0 += 16) {
#pragma unroll
        for (int i = 0; i < 4; i++) {
            int lin = tid + 256 * i;
            int dl = lin >> 4, cc = lin & 15;
            Ws[cc][dl] = W[(size_t)(d0 + dl) * CIN + c0 + cc];
        }
#pragma unroll
        for (int i = 0; i < 8; i++) {
            int lin = tid + 256 * i;
            int cc = lin >> 7, nl = lin & 127;
            Zs[cc][nl] = z[((size_t)b * CIN + c0 + cc) * NN + n0 + nl];
        }
        __syncthreads();
#pragma unroll
        for (int cc = 0; cc < 16; cc++) {
            float4 av = *(const float4*)&Ws[cc][tk * 4];
            float4 b0 = *(const float4*)&Zs[cc][tn * 8];
            float4 b1 = *(const float4*)&Zs[cc][tn * 8 + 4];
            float a[4] = {av.x, av.y, av.z, av.w};
            float bv[8] = {b0.x, b0.y, b0.z, b0.w, b1.x, b1.y, b1.z, b1.w};
#pragma unroll
            for (int i = 0; i < 4; i++)
#pragma unroll
                for (int j = 0; j < 8; j++) acc[i][j] += a[i] * bv[j];
        }
        __syncthreads();
    }
#pragma unroll
    for (int i = 0; i < 4; i++) {
        int d = d0 + tk * 4 + i;
        float* dst = &g_ze[((size_t)b * DDIM + d) * NN + n0 + tn * 8];
        *(float4*)dst       = make_float4(acc[i][0], acc[i][1], acc[i][2], acc[i][3]);
        *(float4*)(dst + 4) = make_float4(acc[i][4], acc[i][5], acc[i][6], acc[i][7]);
    }
}

// ============================================================
// 2-plane bf16 split helpers
// ============================================================
__device__ __forceinline__ void split2(float x, __nv_bfloat16& h, __nv_bfloat16& m) {
    h = __float2bfloat16(x);
    m = __float2bfloat16(x - __bfloat162float(h));
}

__global__ void split_emb_kernel(const float* __restrict__ emb) {
    int i = blockIdx.x * blockDim.x + threadIdx.x;
    if (i >= KKE * DDIM) return;
    __nv_bfloat16 h, m;
    split2(emb[i], h, m);
    g_embb[i] = h;
    g_embb[(size_t)KKE * DDIM + i] = m;
}

// transpose + split ze -> g_zeb planes, plus fp32 transpose -> g_zet
__global__ void split_ze_kernel() {
    __shared__ float tile[64][65];
    const int n0 = blockIdx.x * 64;
    const int d0 = blockIdx.y * 64;
    const int b  = blockIdx.z;
    const int tid = threadIdx.x;
    const size_t ZP = (size_t)BB * NN * DDIM;
#pragma unroll
    for (int i = 0; i < 16; i++) {
        int idx = tid + 256 * i;
        int r = idx >> 6, cc = idx & 63;
        tile[r][cc] = g_ze[((size_t)b * DDIM + d0 + r) * NN + n0 + cc];
    }
    __syncthreads();
#pragma unroll
    for (int i = 0; i < 16; i++) {
        int idx = tid + 256 * i;
        int nr = idx >> 6, dc = idx & 63;
        float x = tile[dc][nr];
        __nv_bfloat16 h, m;
        split2(x, h, m);
        size_t base = ((size_t)b * NN + n0 + nr) * DDIM + d0 + dc;
        g_zeb[base] = h;
        g_zeb[ZP + base] = m;
        g_zet[base] = x;
    }
}

// ============================================================
// znorm: one warp per column, from g_zet
// ============================================================
__global__ void znorm_kernel() {
    const int wid = threadIdx.x >> 5;
    const int L = threadIdx.x & 31;
    const int n = blockIdx.x * 8 + wid;
    const int b = blockIdx.y;
    const size_t cidx = (size_t)b * NN + n;
    const float* zr = g_zet + cidx * DDIM;
    float s = 0.f;
    float4 v0 = *(const float4*)(zr + L * 8);
    float4 v1 = *(const float4*)(zr + L * 8 + 4);
    s = v0.x*v0.x + v0.y*v0.y + v0.z*v0.z + v0.w*v0.w
      + v1.x*v1.x + v1.y*v1.y + v1.z*v1.z + v1.w*v1.w;
#pragma unroll
    for (int off = 16; off; off >>= 1) s += __shfl_xor_sync(0xffffffffu, s, off);
    if (L == 0) g_znorm[cidx] = sqrtf(s);
}

// ============================================================
// Pass A: 3-term approximate score GEMM + rigorous candidate
// collection. CTA: k streamed (16 tiles of 128), 64 n-cols resident.
// 8 warps = 4(M) x 2(N); warp tile 32k x 32n; same fragment
// mapping as validated R6/R7.
// ============================================================
#define PLANE_B 32768
#define OFF_B   (2 * PLANE_B)          // 65536
#define OFF_CTRL (4 * PLANE_B)         // 131072
#define SMEM_ARG (OFF_CTRL + 6144)

__global__ void __launch_bounds__(256, 1) argmin_approx_kernel()
{
    extern __shared__ char smem[];
    char* As = smem;                 // 2 planes x [k_local 128][256B swizzled]
    char* Bs = smem + OFF_B;         // 2 planes x [n_local 64][512B swizzled]
    unsigned int* colthr  = (unsigned int*)(smem + OFF_CTRL);        // [64]
    unsigned int* cnt_s   = (unsigned int*)(smem + OFF_CTRL + 256);  // [64]
    float* znorm_s        = (float*)(smem + OFF_CTRL + 512);         // [64]
    float* esq_s          = (float*)(smem + OFF_CTRL + 768);         // [128]
    float* enorm_s        = (float*)(smem + OFF_CTRL + 1280);        // [128]
    unsigned int* cand_s  = (unsigned int*)(smem + OFF_CTRL + 1792); // [64*CAP]

    const int tid = threadIdx.x;
    const int wid = tid >> 5;
    const int L   = tid & 31;
    const int n0  = blockIdx.x * 64;
    const int b   = blockIdx.y;
    const int wM  = wid >> 1;        // 0..3
    const int wN  = wid & 1;         // 0..1

    const uint32_t As_u = smem_u32(As);
    const uint32_t Bs_u = smem_u32(Bs);
    const size_t ZP = (size_t)BB * NN * DDIM;

    if (tid < 64) {
        colthr[tid] = 0xFFFFFFFFu;
        cnt_s[tid] = 0u;
        znorm_s[tid] = g_znorm[(size_t)b * NN + n0 + tid];
    }

    // ---- load resident B planes (full d, swizzled) ----
#pragma unroll 4
    for (int q = 0; q < 16; q++) {
        int i = tid + 256 * q;               // 0..4095
        int p = i >> 11;
        int rem = i & 2047;
        int r = rem >> 5, c16 = rem & 31;    // 64 rows x 32 granules
        uint4 v = *(const uint4*)&g_zeb[p * ZP + ((size_t)b * NN + n0 + r) * DDIM + c16 * 8];
        *(uint4*)(Bs + p * PLANE_B + r * 512 + ((c16 ^ (r & 7)) * 16)) = v;
    }

    // per-lane static LDSM address components (validated R6/R7)
    const int rowA_l = L & 15;
    const int kxA    = L >> 4;
    const int rowB_l = (L & 7) | ((L & 16) >> 1);
    const int kxB    = (L >> 3) & 1;

    const int PA[3] = {0, 0, 1};
    const int PB[3] = {0, 1, 0};

    for (int kt = 0; kt < 16; kt++) {
        const int k0 = kt * 128;

        float acc[2][4][4];
#pragma unroll
        for (int m = 0; m < 2; m++)
#pragma unroll
            for (int j = 0; j < 4; j++)
#pragma unroll
                for (int r = 0; r < 4; r++) acc[m][j][r] = 0.f;

#pragma unroll 1
        for (int dch = 0; dch < 2; dch++) {
            __syncthreads();
            // ---- load A d-chunk: 2 planes x 128 rows x 256B ----
#pragma unroll 4
            for (int q = 0; q < 16; q++) {
                int i = tid + 256 * q;           // 0..4095
                int p = i >> 11;
                int rem = i & 2047;
                int r = rem >> 4, g = rem & 15;  // 128 rows x 16 granules
                uint4 v = *(const uint4*)&g_embb[((size_t)p * KKE + k0 + r) * DDIM + dch * 128 + g * 8];
                *(uint4*)(As + p * PLANE_B + r * 256 + ((g ^ (r & 7)) * 16)) = v;
            }
            if (dch == 0 && tid < 128) {
                esq_s[tid] = g_esq[k0 + tid];
                enorm_s[tid] = g_enorm[k0 + tid];
            }
            __syncthreads();

#pragma unroll 1
            for (int t = 0; t < 3; t++) {
                const uint32_t Abase = As_u + PA[t] * PLANE_B;
                const uint32_t Bbase = Bs_u + PB[t] * PLANE_B;
#pragma unroll
                for (int dc = 0; dc < 8; dc++) {
                    uint32_t a[2][4], bfr[2][4];
                    {
                        int rA0 = wM * 32 + rowA_l;
                        int gA  = dc * 2 + kxA;
                        ldsm_x4(a[0][0], a[0][1], a[0][2], a[0][3],
                                Abase + rA0 * 256 + ((gA ^ (rA0 & 7)) * 16));
                        int rA1 = rA0 + 16;
                        ldsm_x4(a[1][0], a[1][1], a[1][2], a[1][3],
                                Abase + rA1 * 256 + ((gA ^ (rA1 & 7)) * 16));
                        int rB0 = wN * 32 + rowB_l;
                        int gB  = dch * 16 + dc * 2 + kxB;
                        ldsm_x4(bfr[0][0], bfr[0][1], bfr[0][2], bfr[0][3],
                                Bbase + rB0 * 512 + ((gB ^ (rB0 & 7)) * 16));
                        int rB1 = rB0 + 16;
                        ldsm_x4(bfr[1][0], bfr[1][1], bfr[1][2], bfr[1][3],
                                Bbase + rB1 * 512 + ((gB ^ (rB1 & 7)) * 16));
                    }
#pragma unroll
                    for (int m = 0; m < 2; m++) {
                        mma16816(acc[m][0], a[m], &bfr[0][0]);
                        mma16816(acc[m][1], a[m], &bfr[0][2]);
                        mma16816(acc[m][2], a[m], &bfr[1][0]);
                        mma16816(acc[m][3], a[m], &bfr[1][2]);
                    }
                }
            }
        }

        // ---- epilogue Phase 1: per-column min of (s + E) ----
        float zn[8];
#pragma unroll
        for (int j = 0; j < 4; j++)
#pragma unroll
            for (int par = 0; par < 2; par++)
                zn[j * 2 + par] = znorm_s[wN * 32 + j * 8 + (L & 3) * 2 + par];

        uint32_t umin[8];
#pragma unroll
        for (int c = 0; c < 8; c++) umin[c] = 0xFFFFFFFFu;

#pragma unroll
        for (int m = 0; m < 2; m++) {
            const int kl0 = wM * 32 + m * 16 + (L >> 2);
            const int kl1 = kl0 + 8;
            const float e0 = esq_s[kl0], e1 = esq_s[kl1];
            const float en0 = C0_BOUND * enorm_s[kl0], en1 = C0_BOUND * enorm_s[kl1];
#pragma unroll
            for (int j = 0; j < 4; j++)
#pragma unroll
                for (int r = 0; r < 4; r++) {
                    const int kh = r >> 1, par = r & 1;
                    float s = fmaf(-2.f, acc[m][j][r], kh ? e1 : e0);
                    float E = (kh ? en1 : en0) * zn[j * 2 + par];
                    uint32_t u = orderable(s + E);
                    if (u < umin[j * 2 + par]) umin[j * 2 + par] = u;
                }
        }
#pragma unroll
        for (int c = 0; c < 8; c++) {
#pragma unroll
            for (int off = 4; off <= 16; off <<= 1) {
                uint32_t o = __shfl_xor_sync(0xffffffffu, umin[c], off);
                if (o < umin[c]) umin[c] = o;
            }
        }
        if (L < 4) {
#pragma unroll
            for (int c = 0; c < 8; c++)
                atomicMin(&colthr[wN * 32 + (c >> 1) * 8 + L * 2 + (c & 1)], umin[c]);
        }
        __syncthreads();

        // ---- epilogue Phase 2: collect candidates ----
#pragma unroll
        for (int m = 0; m < 2; m++) {
            const int kl0 = wM * 32 + m * 16 + (L >> 2);
            const int kl1 = kl0 + 8;
            const float e0 = esq_s[kl0], e1 = esq_s[kl1];
            const float en0 = C0_BOUND * enorm_s[kl0], en1 = C0_BOUND * enorm_s[kl1];
#pragma unroll
            for (int j = 0; j < 4; j++)
#pragma unroll
                for (int r = 0; r < 4; r++) {
                    const int kh = r >> 1, par = r & 1;
                    const int col = wN * 32 + j * 8 + (L & 3) * 2 + par;
                    float s = fmaf(-2.f, acc[m][j][r], kh ? e1 : e0);
                    float E = (kh ? en1 : en0) * zn[j * 2 + par];
                    if (orderable(s - E) <= colthr[col]) {
                        unsigned pos = atomicAdd(&cnt_s[col], 1u);
                        if (pos < CAP)
                            cand_s[col * CAP + pos] = (unsigned)(k0 + (kh ? kl1 : kl0));
                    }
                }
        }
    }
    __syncthreads();
    // ---- write candidate lists to global ----
    if (tid < 64) g_ccnt[(size_t)b * NN + n0 + tid] = cnt_s[tid];
#pragma unroll
    for (int q = 0; q < 4; q++) {
        int i = tid + 256 * q;                  // 0..1023
        int lc = i >> 4, slot = i & 15;
        g_cand[((size_t)b * NN + n0 + lc) * CAP + slot] = cand_s[i];
    }
}

// ============================================================
// Pass B: exact fp32 refinement. One warp per column.
// ============================================================
__global__ void refine_kernel(const float* __restrict__ emb) {
    const int wid = threadIdx.x >> 5;
    const int L = threadIdx.x & 31;
    const int n = blockIdx.x * 8 + wid;
    const int b = blockIdx.y;
    const size_t cidx = (size_t)b * NN + n;
    const float* zr = g_zet + cidx * DDIM;

    const float4 z0 = *(const float4*)(zr + L * 8);
    const float4 z1 = *(const float4*)(zr + L * 8 + 4);

    const unsigned cnt = g_ccnt[cidx];
    unsigned long long best = 0xFFFFFFFFFFFFFFFFull;

    if (cnt <= CAP) {
        for (unsigned i = 0; i < cnt; i++) {
            const unsigned k = g_cand[cidx * CAP + i];
            const float* er = emb + (size_t)k * DDIM;
            float4 e0 = *(const float4*)(er + L * 8);
            float4 e1 = *(const float4*)(er + L * 8 + 4);
            float d = e0.x*z0.x;
            d = fmaf(e0.y, z0.y, d); d = fmaf(e0.z, z0.z, d); d = fmaf(e0.w, z0.w, d);
            d = fmaf(e1.x, z1.x, d); d = fmaf(e1.y, z1.y, d);
            d = fmaf(e1.z, z1.z, d); d = fmaf(e1.w, z1.w, d);
#pragma unroll
            for (int off = 16; off; off >>= 1) d += __shfl_xor_sync(0xffffffffu, d, off);
            float s = fmaf(-2.f, d, g_esq[k]);
            unsigned long long pk = ((unsigned long long)orderable(s) << 32) | k;
            if (pk < best) best = pk;
        }
    } else {
        // overflow fallback: exact scan of all codes, lane-strided
        for (int k = L; k < KKE; k += 32) {
            const float* er = emb + (size_t)k * DDIM;
            float d = 0.f;
#pragma unroll 8
            for (int v = 0; v < 64; v++) {
                float4 e4 = *(const float4*)(er + v * 4);
                float4 z4 = *(const float4*)(zr + v * 4);
                d = fmaf(e4.x, z4.x, d); d = fmaf(e4.y, z4.y, d);
                d = fmaf(e4.z, z4.z, d); d = fmaf(e4.w, z4.w, d);
            }
            float s = fmaf(-2.f, d, g_esq[k]);
            unsigned long long pk = ((unsigned long long)orderable(s) << 32) | (unsigned)k;
            if (pk < best) best = pk;
        }
#pragma unroll
        for (int off = 16; off; off >>= 1) {
            unsigned long long o = __shfl_xor_sync(0xffffffffu, best, off);
            if (o < best) best = o;
        }
    }
    if (L == 0) g_minidx[cidx] = (int)(best & 0xFFFFFFFFull);
}

// ============================================================
// zero scatter buffers
// ============================================================
__global__ void zero_kernel() {
    int total = KKE * DDIM + KKE;
    for (int i = blockIdx.x * blockDim.x + threadIdx.x; i < total;
         i += gridDim.x * blockDim.x) {
        if (i < KKE * DDIM) g_zsum[i] = 0.f;
        else g_nsum[i - KKE * DDIM] = 0.f;
    }
}

// ============================================================
// gather zq -> out, scatter-add ze into z_sum / n_sum
// ============================================================
__global__ void gs_kernel(const float* __restrict__ emb, float* __restrict__ out)
{
    const int b = blockIdx.y;
    const int n = blockIdx.x * 32 + threadIdx.x;
    const int ty = threadIdx.y;
    const int idx = g_minidx[(size_t)b * NN + n];
#pragma unroll 4
    for (int d = ty; d < DDIM; d += 8) {
        size_t zoff = ((size_t)b * DDIM + d) * NN + n;
        float zev = g_ze[zoff];
        out[zoff] = emb[(size_t)idx * DDIM + d];
        atomicAdd(&g_zsum[(size_t)idx * DDIM + d], zev);
    }
    if (ty == 0) atomicAdd(&g_nsum[idx], 1.0f);
}

// ============================================================
// EMA finalize -> tail of d_out
// ============================================================
__global__ void ema_kernel(const float* __restrict__ ema_numer,
                           const float* __restrict__ ema_denom,
                           float* __restrict__ out)
{
    const size_t OUT_OFF = (size_t)BB * DDIM * NN;
    int i = blockIdx.x * blockDim.x + threadIdx.x;
    if (i < KKE * DDIM)
        out[OUT_OFF + i] = 0.99f * ema_numer[i] + 0.01f * g_zsum[i];
    if (i < KKE)
        out[OUT_OFF + (size_t)KKE * DDIM + i] = 0.99f * ema_denom[i] + 0.01f * g_nsum[i];
}

// ============================================================
extern "C" void kernel_launch(void* const* d_in, const int* in_sizes, int n_in,
                              void* d_out, int out_size)
{
    const float* z         = (const float*)d_in[0];
    const float* W         = (const float*)d_in[1];
    const float* emb       = (const float*)d_in[2];
    const float* ema_numer = (const float*)d_in[3];
    const float* ema_denom = (const float*)d_in[4];
    float* out = (float*)d_out;
    (void)in_sizes; (void)n_in; (void)out_size;

    cudaFuncSetAttribute(argmin_approx_kernel,
                         cudaFuncAttributeMaxDynamicSharedMemorySize, SMEM_ARG);

    // 1. codebook norms + 2-plane bf16 split of emb
    esq_kernel<<<(KKE * 32 + 255) / 256, 256>>>(emb);
    split_emb_kernel<<<(KKE * DDIM + 255) / 256, 256>>>(emb);

    // 2. ze = W * z  (1x1 conv, fp32)
    {
        dim3 grid(NN / 128, DDIM / 64, BB);
        gemm1_kernel<<<grid, 256>>>(z, W);
    }

    // 3. split + transpose ze (bf16 planes + fp32 transpose)
    {
        dim3 grid(NN / 64, DDIM / 64, BB);
        split_ze_kernel<<<grid, 256>>>();
    }

    // 4. column norms
    {
        dim3 grid(NN / 8, BB);
        znorm_kernel<<<grid, 256>>>();
    }

    // 5. Pass A: 3-term approx GEMM + candidate collection
    {
        dim3 grid(NN / 64, BB);
        argmin_approx_kernel<<<grid, 256, SMEM_ARG>>>();
    }

    // 6. Pass B: exact refinement -> g_minidx
    {
        dim3 grid(NN / 8, BB);
        refine_kernel<<<grid, 256>>>(emb);
    }

    // 7. zero scatter buffers
    zero_kernel<<<512, 256>>>();

    // 8. gather zq + scatter EMA statistics
    {
        dim3 grid(NN / 32, BB);
        dim3 blk(32, 8);
        gs_kernel<<<grid, blk>>>(emb, out);
    }

    // 9. EMA blend
    ema_kernel<<<(KKE * DDIM + 255) / 256, 256>>>(ema_numer, ema_denom, out);
}